// round 1
// baseline (speedup 1.0000x reference)
#include <cuda_runtime.h>
#include <cstddef>

#define B_WIN 4096
#define SEQ   49
#define CDIM  512
#define NH    16
#define HD    32
#define NW    64
#define MROWS (B_WIN * SEQ)      // 200704

// Scratch (no cudaMalloc allowed): QKV intermediate + attention output
__device__ float g_qkv[(size_t)MROWS * 1536];   // [B*N, 3*C]
__device__ float g_att[(size_t)MROWS * CDIM];   // [B*N, C]  (b, n, h, d)

// ---------------------------------------------------------------------------
// 128x128x8 fp32 tiled SGEMM with fused bias: C = A[MxK] @ B[KxN] + bias[N]
// 256 threads, 8x8 microtile per thread. M,N assumed multiples of 128, K of 8.
// ---------------------------------------------------------------------------
#define BM 128
#define BN 128
#define BK 8
#define TM 8
#define TN 8

__global__ __launch_bounds__(256) void sgemm_bias(
    const float* __restrict__ A, const float* __restrict__ B,
    const float* __restrict__ bias, float* __restrict__ C,
    int M, int N, int K)
{
    __shared__ float As[BK][BM];
    __shared__ float Bs[BK][BN];

    const int bx = blockIdx.x;          // N tile
    const int by = blockIdx.y;          // M tile
    const int tid = threadIdx.x;
    const int tx = tid & 15;            // 0..15 (N dir)
    const int ty = tid >> 4;            // 0..15 (M dir)

    // A tile load: 128 rows x 8 cols = 256 float4 (row-major A)
    const int aRow = tid >> 1;           // 0..127
    const int aCol = (tid & 1) << 2;     // 0 or 4
    // B tile load: 8 rows x 128 cols = 256 float4 (row-major B)
    const int bRow = tid >> 5;           // 0..7
    const int bCol = (tid & 31) << 2;    // 0..124

    const float* Ablk = A + (size_t)by * BM * K;
    const float* Bblk = B + (size_t)bx * BN;

    float acc[TM][TN] = {};
    float ar[TM], br[TN];

    for (int k0 = 0; k0 < K; k0 += BK) {
        float4 a4 = *(const float4*)(Ablk + (size_t)aRow * K + k0 + aCol);
        As[aCol + 0][aRow] = a4.x;
        As[aCol + 1][aRow] = a4.y;
        As[aCol + 2][aRow] = a4.z;
        As[aCol + 3][aRow] = a4.w;
        *(float4*)&Bs[bRow][bCol] =
            *(const float4*)(Bblk + (size_t)(k0 + bRow) * N + bCol);
        __syncthreads();

#pragma unroll
        for (int kk = 0; kk < BK; kk++) {
#pragma unroll
            for (int i = 0; i < TM; i++) ar[i] = As[kk][ty * TM + i];
#pragma unroll
            for (int j = 0; j < TN; j++) br[j] = Bs[kk][tx * TN + j];
#pragma unroll
            for (int i = 0; i < TM; i++)
#pragma unroll
                for (int j = 0; j < TN; j++)
                    acc[i][j] += ar[i] * br[j];
        }
        __syncthreads();
    }

#pragma unroll
    for (int i = 0; i < TM; i++) {
        const int row = by * BM + ty * TM + i;
#pragma unroll
        for (int j = 0; j < TN; j += 4) {
            const int col = bx * BN + tx * TN + j;
            float4 o;
            o.x = acc[i][j + 0] + bias[col + 0];
            o.y = acc[i][j + 1] + bias[col + 1];
            o.z = acc[i][j + 2] + bias[col + 2];
            o.w = acc[i][j + 3] + bias[col + 3];
            *(float4*)(C + (size_t)row * N + col) = o;
        }
    }
}

// ---------------------------------------------------------------------------
// Fused attention: one block per (window b, head h).
// scores = scale*q@k^T + rel_bias + window_mask ; softmax ; out = scores @ v
// Writes g_att in [b, n, h, d] layout (= [B*N, C] for the proj GEMM).
// ---------------------------------------------------------------------------
__global__ __launch_bounds__(256) void attn_kernel(
    const float* __restrict__ qkv, const float* __restrict__ mask,
    const float* __restrict__ table, const int* __restrict__ idx,
    float* __restrict__ out)
{
    const int bh = blockIdx.x;
    const int b = bh >> 4;      // / NH
    const int h = bh & 15;
    const int tid = threadIdx.x;

    __shared__ float qs[SEQ * 33];   // stride-33 pad: conflict-free
    __shared__ float ks[SEQ * 33];
    __shared__ float vs[SEQ * 33];
    __shared__ float sc[SEQ * SEQ];

    const float scale = 0.17677669529663687f;   // 32^-0.5
    const size_t rowbase = (size_t)b * SEQ * 1536;
    const int cq = h * HD, ck = 512 + h * HD, cv = 1024 + h * HD;

    // Load q (pre-scaled), k, v tiles: 49x32 each
    for (int i = tid; i < SEQ * HD; i += 256) {
        const int n = i >> 5, d = i & 31;
        const float* r = qkv + rowbase + (size_t)n * 1536;
        qs[n * 33 + d] = r[cq + d] * scale;
        ks[n * 33 + d] = r[ck + d];
        vs[n * 33 + d] = r[cv + d];
    }
    __syncthreads();

    // Scores + bias + mask
    const float* mrow = mask + (size_t)(b & (NW - 1)) * SEQ * SEQ;
    for (int p = tid; p < SEQ * SEQ; p += 256) {
        const int n = p / SEQ, m = p - n * SEQ;
        float s = 0.f;
#pragma unroll
        for (int d = 0; d < HD; d++) s += qs[n * 33 + d] * ks[m * 33 + d];
        s += table[idx[p] * NH + h] + mrow[p];
        sc[p] = s;
    }
    __syncthreads();

    // Row softmax: warp w handles rows w, w+8, ...
    const int warp = tid >> 5, lane = tid & 31;
    for (int r = warp; r < SEQ; r += 8) {
        float v0 = sc[r * SEQ + lane];
        float v1 = (lane < SEQ - 32) ? sc[r * SEQ + 32 + lane] : -1e30f;
        float mx = fmaxf(v0, v1);
#pragma unroll
        for (int o = 16; o > 0; o >>= 1)
            mx = fmaxf(mx, __shfl_xor_sync(0xffffffffu, mx, o));
        float e0 = __expf(v0 - mx);
        float e1 = (lane < SEQ - 32) ? __expf(v1 - mx) : 0.f;
        float sm = e0 + e1;
#pragma unroll
        for (int o = 16; o > 0; o >>= 1)
            sm += __shfl_xor_sync(0xffffffffu, sm, o);
        const float inv = __frcp_rn(sm);
        sc[r * SEQ + lane] = e0 * inv;
        if (lane < SEQ - 32) sc[r * SEQ + 32 + lane] = e1 * inv;
    }
    __syncthreads();

    // out = P @ V  -> [b, n, h, d]
    for (int i = tid; i < SEQ * HD; i += 256) {
        const int n = i >> 5, d = i & 31;
        float acc = 0.f;
#pragma unroll
        for (int m = 0; m < SEQ; m++) acc += sc[n * SEQ + m] * vs[m * 33 + d];
        out[(size_t)(b * SEQ + n) * CDIM + h * HD + d] = acc;
    }
}

// ---------------------------------------------------------------------------
extern "C" void kernel_launch(void* const* d_in, const int* in_sizes, int n_in,
                              void* d_out, int out_size)
{
    const float* x      = (const float*)d_in[0];
    const float* mask   = (const float*)d_in[1];
    const float* qkv_w  = (const float*)d_in[2];
    const float* qkv_b  = (const float*)d_in[3];
    const float* proj_w = (const float*)d_in[4];
    const float* proj_b = (const float*)d_in[5];
    const float* table  = (const float*)d_in[6];
    const int*   idx    = (const int*)d_in[7];
    float* out = (float*)d_out;

    float *qkv_s, *att_s;
    cudaGetSymbolAddress((void**)&qkv_s, g_qkv);
    cudaGetSymbolAddress((void**)&att_s, g_att);

    // 1) QKV projection: [200704,512] @ [512,1536] + bias
    sgemm_bias<<<dim3(1536 / BN, MROWS / BM), 256>>>(
        x, qkv_w, qkv_b, qkv_s, MROWS, 1536, 512);

    // 2) Fused window attention (65536 = 4096 windows * 16 heads)
    attn_kernel<<<B_WIN * NH, 256>>>(qkv_s, mask, table, idx, att_s);

    // 3) Output projection: [200704,512] @ [512,512] + bias
    sgemm_bias<<<dim3(512 / BN, MROWS / BM), 256>>>(
        att_s, proj_w, proj_b, out, MROWS, 512, 512);
}

// round 3
// speedup vs baseline: 1.6806x; 1.6806x over previous
#include <cuda_runtime.h>
#include <cuda_bf16.h>
#include <cstdint>
#include <cstddef>

#define B_WIN 4096
#define SEQ   49
#define CDIM  512
#define NH    16
#define HD    32
#define NW    64
#define MROWS (B_WIN * SEQ)      // 200704
#define KDIM  512

// ---------------- device scratch (no cudaMalloc allowed) -------------------
__device__ float g_qkv[(size_t)MROWS * 1536];             // [B*N, 3C] fp32
__device__ __nv_bfloat16 g_x_hi[(size_t)MROWS * KDIM];    // x split
__device__ __nv_bfloat16 g_x_lo[(size_t)MROWS * KDIM];
__device__ __nv_bfloat16 g_att_hi[(size_t)MROWS * KDIM];  // attn out split
__device__ __nv_bfloat16 g_att_lo[(size_t)MROWS * KDIM];
__device__ __nv_bfloat16 g_qw_hi[1536 * KDIM];            // qkv_w^T split [N,K]
__device__ __nv_bfloat16 g_qw_lo[1536 * KDIM];
__device__ __nv_bfloat16 g_pw_hi[512 * KDIM];             // proj_w^T split [N,K]
__device__ __nv_bfloat16 g_pw_lo[512 * KDIM];

// ---------------- helpers (all arch-portable PTX: sm_80+ features) ---------
__device__ __forceinline__ uint32_t smem_u32(const void* p) {
    uint32_t a;
    asm("{ .reg .u64 t; cvta.to.shared.u64 t, %1; cvt.u32.u64 %0, t; }"
        : "=r"(a) : "l"(p));
    return a;
}
#define CPA16(dst, src) \
    asm volatile("cp.async.cg.shared.global [%0], [%1], 16;" \
                 :: "r"(dst), "l"(src) : "memory")
#define CPCOMMIT() asm volatile("cp.async.commit_group;" ::: "memory")
#define CPWAIT(n)  asm volatile("cp.async.wait_group %0;" :: "n"(n) : "memory")
#define LDSM4(r, addr)                                                        \
    asm volatile("ldmatrix.sync.aligned.m8n8.x4.shared.b16 {%0,%1,%2,%3}, [%4];" \
        : "=r"((r)[0]), "=r"((r)[1]), "=r"((r)[2]), "=r"((r)[3]) : "r"(addr))
#define MMA_BF16(d, a, b0, b1)                                                \
    asm volatile("mma.sync.aligned.m16n8k16.row.col.f32.bf16.bf16.f32 "       \
        "{%0,%1,%2,%3},{%4,%5,%6,%7},{%8,%9},{%0,%1,%2,%3};"                  \
        : "+f"((d)[0]), "+f"((d)[1]), "+f"((d)[2]), "+f"((d)[3])              \
        : "r"((a)[0]), "r"((a)[1]), "r"((a)[2]), "r"((a)[3]),                 \
          "r"(b0), "r"(b1))

__device__ __forceinline__ uint32_t pack_bf2(__nv_bfloat16 a, __nv_bfloat16 b) {
    uint16_t ua = *reinterpret_cast<uint16_t*>(&a);
    uint16_t ub = *reinterpret_cast<uint16_t*>(&b);
    return (uint32_t)ua | ((uint32_t)ub << 16);
}
__device__ __forceinline__ void split_pair(float a, float b, uint32_t& hi, uint32_t& lo) {
    __nv_bfloat16 ha = __float2bfloat16_rn(a), hb = __float2bfloat16_rn(b);
    hi = pack_bf2(ha, hb);
    float ra = a - __bfloat162float(ha), rb = b - __bfloat162float(hb);
    lo = pack_bf2(__float2bfloat16_rn(ra), __float2bfloat16_rn(rb));
}

// ---------------------------------------------------------------------------
// fp32 -> bf16 hi/lo split (element-wise, for activations)
// ---------------------------------------------------------------------------
__global__ void fsplit(const float4* __restrict__ in, uint2* __restrict__ hi,
                       uint2* __restrict__ lo, int n4)
{
    const int i = blockIdx.x * blockDim.x + threadIdx.x;
    if (i >= n4) return;
    float4 v = in[i];
    uint2 H, L;
    split_pair(v.x, v.y, H.x, L.x);
    split_pair(v.z, v.w, H.y, L.y);
    hi[i] = H;
    lo[i] = L;
}

// ---------------------------------------------------------------------------
// Weight prep: W[K,N] fp32 -> Bhi/Blo[N,K] bf16 (transposed + split)
// ---------------------------------------------------------------------------
__global__ void wsplit(const float* __restrict__ W, __nv_bfloat16* __restrict__ Bhi,
                       __nv_bfloat16* __restrict__ Blo, int K, int N)
{
    __shared__ float t[32][33];
    const int bx = blockIdx.x, by = blockIdx.y;
    const int x = threadIdx.x, y = threadIdx.y;   // 32 x 8
#pragma unroll
    for (int i = 0; i < 4; i++)
        t[y + i * 8][x] = W[(size_t)(by * 32 + y + i * 8) * N + bx * 32 + x];
    __syncthreads();
#pragma unroll
    for (int i = 0; i < 4; i++) {
        float v = t[x][y + i * 8];
        __nv_bfloat16 h = __float2bfloat16_rn(v);
        size_t o = (size_t)(bx * 32 + y + i * 8) * K + by * 32 + x;
        Bhi[o] = h;
        Blo[o] = __float2bfloat16_rn(v - __bfloat162float(h));
    }
}

// ---------------------------------------------------------------------------
// bf16 mma.sync GEMM with 3-term split:
//   C[M,Ntot] = (Ahi+Alo)[M,512] @ (Bhi+Blo)[N,512]^T + bias
// CTA 128x128, BK=32, cp.async double buffer, 8 warps x (64x32) each.
// SMEM rows stride 80B -> conflict-free ldmatrix.
// ---------------------------------------------------------------------------
#define RS        80
#define AT_BYTES  (128 * RS)        // 10240 per tensor tile
#define STAGE     (4 * AT_BYTES)    // 40960 per stage
#define GSMEM     (2 * STAGE)       // 81920

__global__ __launch_bounds__(256)
void gemm_bf16(const __nv_bfloat16* __restrict__ Ahi_g,
               const __nv_bfloat16* __restrict__ Alo_g,
               const __nv_bfloat16* __restrict__ Bhi_g,
               const __nv_bfloat16* __restrict__ Blo_g,
               const float* __restrict__ bias, float* __restrict__ C, int Ntot)
{
    extern __shared__ __align__(128) char sm[];
    const uint32_t sb = smem_u32(sm);
    const int tid = threadIdx.x;
    const int lane = tid & 31, wid = tid >> 5;
    const int m0 = blockIdx.y * 128, n0 = blockIdx.x * 128;
    const int wm = (wid >> 2) * 64, wn = (wid & 3) * 32;

    // copy roles: thread -> (row, 32B half of the 64B k-chunk)
    const int crow = tid >> 1;
    const int cc   = (tid & 1) * 32;

    const char* gsrc0 = (const char*)(Ahi_g + (size_t)m0 * KDIM);
    const char* gsrc1 = (const char*)(Alo_g + (size_t)m0 * KDIM);
    const char* gsrc2 = (const char*)(Bhi_g + (size_t)n0 * KDIM);
    const char* gsrc3 = (const char*)(Blo_g + (size_t)n0 * KDIM);

    float acc[4][4][4];
#pragma unroll
    for (int a = 0; a < 4; a++)
#pragma unroll
        for (int b = 0; b < 4; b++)
#pragma unroll
            for (int c = 0; c < 4; c++) acc[a][b][c] = 0.f;

    auto issue = [&](int s, int kc) {
        const int gofs = crow * 1024 + kc * 64 + cc;   // 512 bf16 = 1024B rows
        const uint32_t dst = sb + s * STAGE + crow * RS + cc;
        CPA16(dst + 0 * AT_BYTES,      gsrc0 + gofs);
        CPA16(dst + 0 * AT_BYTES + 16, gsrc0 + gofs + 16);
        CPA16(dst + 1 * AT_BYTES,      gsrc1 + gofs);
        CPA16(dst + 1 * AT_BYTES + 16, gsrc1 + gofs + 16);
        CPA16(dst + 2 * AT_BYTES,      gsrc2 + gofs);
        CPA16(dst + 2 * AT_BYTES + 16, gsrc2 + gofs + 16);
        CPA16(dst + 3 * AT_BYTES,      gsrc3 + gofs);
        CPA16(dst + 3 * AT_BYTES + 16, gsrc3 + gofs + 16);
        CPCOMMIT();
    };

    issue(0, 0);
    issue(1, 1);

    const int r = lane & 15;
    const uint32_t khalf = (lane >> 4) * 16;

    for (int kc = 0; kc < 16; kc++) {
        const int s = kc & 1;
        if (kc < 15) { CPWAIT(1); } else { CPWAIT(0); }
        __syncthreads();

        const uint32_t base = sb + s * STAGE;
#pragma unroll
        for (int kk = 0; kk < 2; kk++) {
            const uint32_t ko = kk * 32 + khalf;
            uint32_t ah[4][4], al[4][4], bh[2][4], bl[2][4];
#pragma unroll
            for (int mt = 0; mt < 4; mt++) {
                const uint32_t ra = base + (uint32_t)(wm + mt * 16 + r) * RS + ko;
                LDSM4(ah[mt], ra);
                LDSM4(al[mt], ra + AT_BYTES);
            }
#pragma unroll
            for (int p = 0; p < 2; p++) {
                const uint32_t rb = base + 2 * AT_BYTES +
                                    (uint32_t)(wn + p * 16 + r) * RS + ko;
                LDSM4(bh[p], rb);
                LDSM4(bl[p], rb + AT_BYTES);
            }
#pragma unroll
            for (int mt = 0; mt < 4; mt++)
#pragma unroll
                for (int nt = 0; nt < 4; nt++) {
                    const int p = nt >> 1, o = nt & 1;
                    MMA_BF16(acc[mt][nt], ah[mt], bh[p][o], bh[p][o + 2]);
                    MMA_BF16(acc[mt][nt], ah[mt], bl[p][o], bl[p][o + 2]);
                    MMA_BF16(acc[mt][nt], al[mt], bh[p][o], bh[p][o + 2]);
                }
        }
        __syncthreads();
        if (kc + 2 < 16) issue(s, kc + 2);
    }

    // epilogue + bias
#pragma unroll
    for (int mt = 0; mt < 4; mt++) {
        const int gr = m0 + wm + mt * 16 + (lane >> 2);
#pragma unroll
        for (int nt = 0; nt < 4; nt++) {
            const int gc = n0 + wn + nt * 8 + (lane & 3) * 2;
            const float b0 = bias[gc], b1 = bias[gc + 1];
            float2 v0 = { acc[mt][nt][0] + b0, acc[mt][nt][1] + b1 };
            float2 v1 = { acc[mt][nt][2] + b0, acc[mt][nt][3] + b1 };
            *(float2*)&C[(size_t)gr * Ntot + gc] = v0;
            *(float2*)&C[(size_t)(gr + 8) * Ntot + gc] = v1;
        }
    }
}

// ---------------------------------------------------------------------------
// Fused window attention; output written pre-split to bf16 hi/lo.
// ---------------------------------------------------------------------------
__global__ __launch_bounds__(256) void attn_kernel(
    const float* __restrict__ qkv, const float* __restrict__ mask,
    const float* __restrict__ table, const int* __restrict__ idx,
    __nv_bfloat16* __restrict__ out_hi, __nv_bfloat16* __restrict__ out_lo)
{
    const int bh = blockIdx.x;
    const int b = bh >> 4, hh = bh & 15;
    const int tid = threadIdx.x;

    __shared__ float qs[SEQ * 33];
    __shared__ float ks[SEQ * 33];
    __shared__ float vs[SEQ * 33];
    __shared__ float sc[SEQ * SEQ];

    const float scale = 0.17677669529663687f;
    const size_t rowbase = (size_t)b * SEQ * 1536;
    const int cq = hh * HD, ck = 512 + hh * HD, cv = 1024 + hh * HD;

    for (int i = tid; i < SEQ * HD; i += 256) {
        const int n = i >> 5, d = i & 31;
        const float* r = qkv + rowbase + (size_t)n * 1536;
        qs[n * 33 + d] = r[cq + d] * scale;
        ks[n * 33 + d] = r[ck + d];
        vs[n * 33 + d] = r[cv + d];
    }
    __syncthreads();

    const float* mrow = mask + (size_t)(b & (NW - 1)) * SEQ * SEQ;
    for (int p = tid; p < SEQ * SEQ; p += 256) {
        const int n = p / SEQ, m = p - n * SEQ;
        float s = 0.f;
#pragma unroll
        for (int d = 0; d < HD; d++) s += qs[n * 33 + d] * ks[m * 33 + d];
        s += table[idx[p] * NH + hh] + mrow[p];
        sc[p] = s;
    }
    __syncthreads();

    const int warp = tid >> 5, lane = tid & 31;
    for (int rr = warp; rr < SEQ; rr += 8) {
        float v0 = sc[rr * SEQ + lane];
        float v1 = (lane < SEQ - 32) ? sc[rr * SEQ + 32 + lane] : -1e30f;
        float mx = fmaxf(v0, v1);
#pragma unroll
        for (int o = 16; o > 0; o >>= 1)
            mx = fmaxf(mx, __shfl_xor_sync(0xffffffffu, mx, o));
        float e0 = __expf(v0 - mx);
        float e1 = (lane < SEQ - 32) ? __expf(v1 - mx) : 0.f;
        float sm = e0 + e1;
#pragma unroll
        for (int o = 16; o > 0; o >>= 1)
            sm += __shfl_xor_sync(0xffffffffu, sm, o);
        const float inv = __frcp_rn(sm);
        sc[rr * SEQ + lane] = e0 * inv;
        if (lane < SEQ - 32) sc[rr * SEQ + 32 + lane] = e1 * inv;
    }
    __syncthreads();

    for (int i = tid; i < SEQ * HD; i += 256) {
        const int n = i >> 5, d = i & 31;
        float acc = 0.f;
#pragma unroll
        for (int m = 0; m < SEQ; m++) acc += sc[n * SEQ + m] * vs[m * 33 + d];
        const size_t o = (size_t)(b * SEQ + n) * CDIM + hh * HD + d;
        __nv_bfloat16 h = __float2bfloat16_rn(acc);
        out_hi[o] = h;
        out_lo[o] = __float2bfloat16_rn(acc - __bfloat162float(h));
    }
}

// ---------------------------------------------------------------------------
extern "C" void kernel_launch(void* const* d_in, const int* in_sizes, int n_in,
                              void* d_out, int out_size)
{
    const float* x      = (const float*)d_in[0];
    const float* mask   = (const float*)d_in[1];
    const float* qkv_w  = (const float*)d_in[2];
    const float* qkv_b  = (const float*)d_in[3];
    const float* proj_w = (const float*)d_in[4];
    const float* proj_b = (const float*)d_in[5];
    const float* table  = (const float*)d_in[6];
    const int*   idx    = (const int*)d_in[7];
    float* out = (float*)d_out;

    float* qkv_s;
    __nv_bfloat16 *xh, *xl, *ah, *al, *qwh, *qwl, *pwh, *pwl;
    cudaGetSymbolAddress((void**)&qkv_s, g_qkv);
    cudaGetSymbolAddress((void**)&xh, g_x_hi);
    cudaGetSymbolAddress((void**)&xl, g_x_lo);
    cudaGetSymbolAddress((void**)&ah, g_att_hi);
    cudaGetSymbolAddress((void**)&al, g_att_lo);
    cudaGetSymbolAddress((void**)&qwh, g_qw_hi);
    cudaGetSymbolAddress((void**)&qwl, g_qw_lo);
    cudaGetSymbolAddress((void**)&pwh, g_pw_hi);
    cudaGetSymbolAddress((void**)&pwl, g_pw_lo);

    cudaFuncSetAttribute(gemm_bf16, cudaFuncAttributeMaxDynamicSharedMemorySize, GSMEM);

    // 0) split x into bf16 hi/lo, weights transpose+split
    const int n4 = MROWS * KDIM / 4;
    fsplit<<<(n4 + 255) / 256, 256>>>((const float4*)x, (uint2*)xh, (uint2*)xl, n4);
    wsplit<<<dim3(1536 / 32, 512 / 32), dim3(32, 8)>>>(qkv_w, qwh, qwl, 512, 1536);
    wsplit<<<dim3(512 / 32, 512 / 32), dim3(32, 8)>>>(proj_w, pwh, pwl, 512, 512);

    // 1) QKV projection (tensor cores via mma.sync)
    gemm_bf16<<<dim3(1536 / 128, MROWS / 128), 256, GSMEM>>>(
        xh, xl, qwh, qwl, qkv_b, qkv_s, 1536);

    // 2) fused window attention (writes split bf16)
    attn_kernel<<<B_WIN * NH, 256>>>(qkv_s, mask, table, idx, ah, al);

    // 3) output projection
    gemm_bf16<<<dim3(512 / 128, MROWS / 128), 256, GSMEM>>>(
        ah, al, pwh, pwl, proj_b, out, 512);
}